// round 4
// baseline (speedup 1.0000x reference)
#include <cuda_runtime.h>
#include <cuda_bf16.h>

// AUCM loss, fully fused single persistent kernel.
//   loss = [ Sum_{ij} (a_i+b_j)^2 + Sum_{ij} relu(a_i+b_j) ] / (np*nn)
//   with a_i = 1 - p_pos_i, b_j = p_neg_j.
// Quadratic term is separable: nn*S(a^2) + 2*S(a)*S(b) + np*S(b^2) -> exact
// from per-block moments (double). Only the relu term is done pairwise:
// each block keeps its local negatives in shared and sweeps all positives.
// Grid barriers are sense-reversal + self-resetting (graph-replay safe);
// all 128 blocks are co-resident on 148 SMs.

#define NB   128      // blocks (must be <= SM count for barrier safety)
#define NT   256      // threads per block
#define SLICE 128     // elements per block (N = 16384)
#define NSEG  (NT / SLICE)   // positive-range segments per block (=2)
#define POS_TILE 8192 // shared positives tile (np ~1200 -> single tile)

__device__ int      g_cnt_pos[NB];
__device__ float    g_pos[16384];
__device__ double   g_part_relu[NB];
__device__ double   g_part_sa [NB];
__device__ double   g_part_sa2[NB];
__device__ double   g_part_sb [NB];
__device__ double   g_part_sb2[NB];
__device__ unsigned g_bar_count = 0;
__device__ volatile unsigned g_bar_sense = 0;
__device__ unsigned g_done = 0;

// warp+shared double reduction; result valid on tid 0
__device__ __forceinline__ double block_reduce_d(double v, double* sh) {
    #pragma unroll
    for (int o = 16; o; o >>= 1) v += __shfl_down_sync(0xffffffffu, v, o);
    int w = threadIdx.x >> 5;
    if ((threadIdx.x & 31) == 0) sh[w] = v;
    __syncthreads();
    if (threadIdx.x < 8) {
        v = sh[threadIdx.x];
        #pragma unroll
        for (int o = 4; o; o >>= 1) v += __shfl_down_sync(0xffu, v, o);
    }
    __syncthreads();
    return v;
}

__global__ void __launch_bounds__(NT, 1) aucm_fused_kernel(
    const float* __restrict__ preds,
    const int*   __restrict__ targets,
    float* __restrict__ out, int n)
{
    __shared__ float  s_neg[SLICE];     // local negatives (persist to phase 3)
    __shared__ float  s_lpos[SLICE];    // local positives (phase 1-2)
    __shared__ float  s_postile[POS_TILE];
    __shared__ double s_red[8];
    __shared__ int    s_np, s_nn, s_posoff, s_nptot;
    __shared__ unsigned s_sense;
    __shared__ int    s_last;

    const int tid = threadIdx.x;
    const int bid = blockIdx.x;

    if (tid == 0) { s_np = 0; s_nn = 0; s_sense = g_bar_sense; }
    __syncthreads();

    // ---- Phase 1: local partition + moments ----
    double va = 0.0, va2 = 0.0, vb = 0.0, vb2 = 0.0;
    if (tid < SLICE) {
        int idx = bid * SLICE + tid;
        float p = preds[idx];
        if (targets[idx] == 1) {
            float a = 1.0f - p;
            int k = atomicAdd(&s_np, 1);
            s_lpos[k] = a;
            va = a; va2 = (double)a * a;
        } else {
            int k = atomicAdd(&s_nn, 1);
            s_neg[k] = p;
            vb = p; vb2 = (double)p * p;
        }
    }
    __syncthreads();

    double r;
    r = block_reduce_d(va,  s_red); if (tid == 0) g_part_sa [bid] = r;
    r = block_reduce_d(va2, s_red); if (tid == 0) g_part_sa2[bid] = r;
    r = block_reduce_d(vb,  s_red); if (tid == 0) g_part_sb [bid] = r;
    r = block_reduce_d(vb2, s_red); if (tid == 0) g_part_sb2[bid] = r;
    if (tid == 0) g_cnt_pos[bid] = s_np;

    // ---- grid barrier 1 ----
    __syncthreads();
    if (tid == 0) {
        unsigned my = s_sense ^ 1; s_sense = my;
        __threadfence();
        if (atomicAdd(&g_bar_count, 1) == NB - 1) {
            g_bar_count = 0; __threadfence(); g_bar_sense = my;
        } else {
            while (g_bar_sense != my) { }
        }
        __threadfence();
    }
    __syncthreads();

    // ---- Phase 2: prefix offsets, publish positives ----
    if (tid == 0) {
        int off = 0, tot = 0;
        #pragma unroll 4
        for (int i = 0; i < NB; i++) {
            int c = __ldcg(&g_cnt_pos[i]);
            if (i < bid) off += c;
            tot += c;
        }
        s_posoff = off; s_nptot = tot;
    }
    __syncthreads();
    for (int k = tid; k < s_np; k += NT)
        g_pos[s_posoff + k] = s_lpos[k];

    // ---- grid barrier 2 ----
    __syncthreads();
    if (tid == 0) {
        unsigned my = s_sense ^ 1; s_sense = my;
        __threadfence();
        if (atomicAdd(&g_bar_count, 1) == NB - 1) {
            g_bar_count = 0; __threadfence(); g_bar_sense = my;
        } else {
            while (g_bar_sense != my) { }
        }
        __threadfence();
    }
    __syncthreads();

    // ---- Phase 3: relu pairwise (local negatives x all positives) ----
    const int np = s_nptot;
    const int nneg = s_nn;
    const int jn  = tid & (SLICE - 1);
    const int seg = tid >> 7;            // 0..NSEG-1
    const bool active = jn < nneg;
    const float bj = active ? s_neg[jn] : 0.0f;

    float acc0 = 0.f, acc1 = 0.f, acc2 = 0.f, acc3 = 0.f;
    for (int t0 = 0; t0 < np; t0 += POS_TILE) {
        const int cnt = min(POS_TILE, np - t0);
        for (int i = tid; i < cnt; i += NT)
            s_postile[i] = __ldcg(&g_pos[t0 + i]);
        __syncthreads();

        if (active) {
            int half = (cnt + NSEG - 1) / NSEG;
            int i0 = seg * half;
            int i1 = min(cnt, i0 + half);
            int i = i0;
            for (; i + 4 <= i1; i += 4) {
                acc0 += fmaxf(s_postile[i    ] + bj, 0.0f);
                acc1 += fmaxf(s_postile[i + 1] + bj, 0.0f);
                acc2 += fmaxf(s_postile[i + 2] + bj, 0.0f);
                acc3 += fmaxf(s_postile[i + 3] + bj, 0.0f);
            }
            for (; i < i1; i++)
                acc0 += fmaxf(s_postile[i] + bj, 0.0f);
        }
        __syncthreads();
    }
    double relu_sum = block_reduce_d(
        (double)((acc0 + acc1) + (acc2 + acc3)), s_red);
    if (tid == 0) g_part_relu[bid] = relu_sum;

    // ---- last-block finalize (self-resetting counter) ----
    __threadfence();
    __syncthreads();
    if (tid == 0) s_last = (atomicAdd(&g_done, 1) == NB - 1);
    __syncthreads();
    if (!s_last) return;

    double pr = 0, psa = 0, psa2 = 0, psb = 0, psb2 = 0;
    if (tid < NB) {
        pr   = __ldcg(&g_part_relu[tid]);
        psa  = __ldcg(&g_part_sa  [tid]);
        psa2 = __ldcg(&g_part_sa2 [tid]);
        psb  = __ldcg(&g_part_sb  [tid]);
        psb2 = __ldcg(&g_part_sb2 [tid]);
    }
    pr   = block_reduce_d(pr,   s_red);
    psa  = block_reduce_d(psa,  s_red);
    psa2 = block_reduce_d(psa2, s_red);
    psb  = block_reduce_d(psb,  s_red);
    psb2 = block_reduce_d(psb2, s_red);
    if (tid == 0) {
        double dnp = (double)s_nptot;
        double dnn = (double)n - dnp;
        double quad = dnn * psa2 + 2.0 * psa * psb + dnp * psb2;
        out[0] = (float)((quad + pr) / (dnp * dnn));
        g_done = 0;
        __threadfence();
    }
}

extern "C" void kernel_launch(void* const* d_in, const int* in_sizes, int n_in,
                              void* d_out, int out_size) {
    const float* preds   = (const float*)d_in[0];
    const int*   targets = (const int*)d_in[1];
    float*       out     = (float*)d_out;
    const int n = in_sizes[0];   // 16384 = NB * SLICE

    aucm_fused_kernel<<<NB, NT>>>(preds, targets, out, n);
}

// round 6
// speedup vs baseline: 1.3705x; 1.3705x over previous
#include <cuda_runtime.h>
#include <cuda_bf16.h>

// AUCM loss, single kernel, NO grid barriers.
//   loss = Sum_{pos i, neg j} [ (a_i+b_j)^2 + relu(a_i+b_j) ] / (np*nn),
//   a_i = 1 - p_pos_i, b_j = p_neg_j.
// Every block redundantly scans the full (preds, targets) arrays (128 KB,
// L2-broadcast across blocks ~ free) and compacts the positives from its
// assigned source half into shared memory. Block (bx, by) computes pairs:
//   negatives { bx*256 + tid } x positives from half `by`.
// Per-block double partial -> one double atomicAdd; self-resetting
// done-counter finalizes (divide + reset state for graph replay).

#define N_ELEMS 16384
#define NT      256
#define NBX     (N_ELEMS / NT)   // 64
#define NBY     2
#define NBLK    (NBX * NBY)      // 128 blocks, one wave on 148 SMs
#define HALF    (N_ELEMS / NBY)  // 8192 source elements per half

__device__ double   g_sum  = 0.0;
__device__ unsigned g_done = 0;

__device__ __forceinline__ double block_reduce_d(double v, double* sh) {
    #pragma unroll
    for (int o = 16; o; o >>= 1) v += __shfl_down_sync(0xffffffffu, v, o);
    int w = threadIdx.x >> 5;
    if ((threadIdx.x & 31) == 0) sh[w] = v;
    __syncthreads();
    if (threadIdx.x < 8) {
        v = sh[threadIdx.x];
        #pragma unroll
        for (int o = 4; o; o >>= 1) v += __shfl_down_sync(0xffu, v, o);
    }
    __syncthreads();
    return v;
}

__global__ void __launch_bounds__(NT, 1) aucm_kernel(
    const float* __restrict__ preds,
    const int*   __restrict__ targets,
    float* __restrict__ out)
{
    __shared__ float  s_pos[HALF];   // worst-case all-positive half: 32 KB
    __shared__ int    s_cnt;
    __shared__ double s_red[8];
    __shared__ int    s_wred[8];
    __shared__ int    s_nptot;

    const int tid = threadIdx.x;
    const int bx  = blockIdx.x;
    const int by  = blockIdx.y;
    const unsigned lane = tid & 31u;

    if (tid == 0) s_cnt = 0;
    __syncthreads();

    // ---- my negative candidate ----
    const int   myidx = bx * NT + tid;
    const float myp   = preds[myidx];
    const bool  isneg = (targets[myidx] == 0);

    // ---- full scan: count all positives; compact my half into shared ----
    const float4* p4 = (const float4*)preds;
    const int4*   t4 = (const int4*)targets;
    int cnt_all = 0;
    for (int i = tid; i < N_ELEMS / 4; i += NT) {
        float4 pv = p4[i];
        int4   tv = t4[i];
        const int e = i * 4;                   // e..e+3 stay in one half (HALF%4==0)
        const bool inhalf = ((e / HALF) == by);
        #pragma unroll
        for (int k = 0; k < 4; k++) {
            int   t  = (&tv.x)[k];
            float pp = (&pv.x)[k];
            bool ispos = (t == 1);
            cnt_all += ispos ? 1 : 0;
            bool push = ispos && inhalf;
            unsigned m = __ballot_sync(0xffffffffu, push);
            if (m) {
                int leader = __ffs(m) - 1;
                int base = 0;
                if ((int)lane == leader) base = atomicAdd(&s_cnt, __popc(m));
                base = __shfl_sync(0xffffffffu, base, leader);
                if (push)
                    s_pos[base + __popc(m & ((1u << lane) - 1u))] = 1.0f - pp;
            }
        }
    }

    // block-reduce total positive count (same value in every block)
    #pragma unroll
    for (int o = 16; o; o >>= 1) cnt_all += __shfl_down_sync(0xffffffffu, cnt_all, o);
    if (lane == 0) s_wred[tid >> 5] = cnt_all;
    __syncthreads();
    if (tid == 0) {
        int t = 0;
        #pragma unroll
        for (int w = 0; w < 8; w++) t += s_wred[w];
        s_nptot = t;
    }
    __syncthreads();

    // ---- pair loop: my negative x positives of my half ----
    const int   cnt = s_cnt;
    const float b   = myp;
    float acc0 = 0.f, acc1 = 0.f, acc2 = 0.f, acc3 = 0.f;
    if (isneg) {
        int i = 0;
        for (; i + 8 <= cnt; i += 8) {
            float d0 = s_pos[i + 0] + b;
            float d1 = s_pos[i + 1] + b;
            float d2 = s_pos[i + 2] + b;
            float d3 = s_pos[i + 3] + b;
            float d4 = s_pos[i + 4] + b;
            float d5 = s_pos[i + 5] + b;
            float d6 = s_pos[i + 6] + b;
            float d7 = s_pos[i + 7] + b;
            acc0 += fmaf(d0, d0, fmaxf(d0, 0.0f));
            acc1 += fmaf(d1, d1, fmaxf(d1, 0.0f));
            acc2 += fmaf(d2, d2, fmaxf(d2, 0.0f));
            acc3 += fmaf(d3, d3, fmaxf(d3, 0.0f));
            acc0 += fmaf(d4, d4, fmaxf(d4, 0.0f));
            acc1 += fmaf(d5, d5, fmaxf(d5, 0.0f));
            acc2 += fmaf(d6, d6, fmaxf(d6, 0.0f));
            acc3 += fmaf(d7, d7, fmaxf(d7, 0.0f));
        }
        for (; i < cnt; i++) {
            float d = s_pos[i] + b;
            acc0 += fmaf(d, d, fmaxf(d, 0.0f));
        }
    }

    double v = (double)((acc0 + acc1) + (acc2 + acc3));
    double r = block_reduce_d(v, s_red);

    // ---- accumulate + last-block finalize (self-resetting) ----
    if (tid == 0) {
        atomicAdd(&g_sum, r);
        __threadfence();
        if (atomicAdd(&g_done, 1u) == NBLK - 1) {
            double total = atomicAdd(&g_sum, 0.0);   // atomic read-after all adds
            double dnp = (double)s_nptot;
            double dnn = (double)N_ELEMS - dnp;
            out[0] = (float)(total / (dnp * dnn));
            g_sum  = 0.0;      // restore state for next graph replay
            g_done = 0u;
            __threadfence();
        }
    }
}

extern "C" void kernel_launch(void* const* d_in, const int* in_sizes, int n_in,
                              void* d_out, int out_size) {
    const float* preds   = (const float*)d_in[0];
    const int*   targets = (const int*)d_in[1];
    float*       out     = (float*)d_out;

    dim3 grid(NBX, NBY);
    aucm_kernel<<<grid, NT>>>(preds, targets, out);
}